// round 9
// baseline (speedup 1.0000x reference)
#include <cuda_runtime.h>

// PatchExtractor3d: out[b, c*27 + i*9 + j*3 + l, d, h, w] = xpad[b, c, d+i, h+j, w+l]
// x [2,3,32,128,128] fp32 -> out [2,81,32,128,128] fp32, pad=1, K=3.
//
// HYBRID: block = (b, c, i, d) -> one input plane feeds the 9 contiguous
// output planes (j,l). Each warp: 16 consecutive h-rows, 18 front-batched
// LDG.128 (slab+halo), then 9 x 16 sequential STG.128 from held registers.
// Gather-style contiguous write streams + scatter-style 1x read traffic.

static constexpr int B_  = 2;
static constexpr int C_  = 3;
static constexpr int D_  = 32;
static constexpr int H_  = 128;
static constexpr int W_  = 128;
static constexpr int COUT = C_ * 27;   // 81
static constexpr int ROWQ = W_ / 4;    // 32 float4 per row

template<int L>
__device__ __forceinline__ float4 shift_row(float4 cur, int lane) {
    if (L == 1) return cur;
    float4 r;
    if (L == 0) {                       // out[w] = in[w-1]
        const float pw = __shfl_up_sync(0xffffffffu, cur.w, 1);
        r.x = (lane == 0) ? 0.f : pw;
        r.y = cur.x; r.z = cur.y; r.w = cur.z;
    } else {                            // out[w] = in[w+1]
        const float nx = __shfl_down_sync(0xffffffffu, cur.x, 1);
        r.x = cur.y; r.y = cur.z; r.z = cur.w;
        r.w = (lane == 31) ? 0.f : nx;
    }
    return r;
}

// Store one (J,L) plane-slab: 16 sequential rows from registers v[k+J].
template<int J, int L>
__device__ __forceinline__ void store_plane(const float4* v,
                                            float4* __restrict__ p /* row h0, this plane */,
                                            int lane) {
    #pragma unroll
    for (int k = 0; k < 16; ++k)
        __stcs(p + (size_t)k * ROWQ, shift_row<L>(v[k + J], lane));
}

__global__ __launch_bounds__(256, 2)
void patch3d_hybrid(const float* __restrict__ x, float* __restrict__ out) {
    const int d   = blockIdx.x;          // 0..31
    const int ci  = blockIdx.y;          // 0..8 : c*3 + i
    const int b   = blockIdx.z;          // 0..1
    const int c   = ci / 3;
    const int i   = ci - c * 3;
    const int din = d + i - 1;

    const int warp = threadIdx.x >> 5;
    const int lane = threadIdx.x & 31;
    const int h0   = warp * 16;

    float4* const out4 = reinterpret_cast<float4*>(out);
    // row index of (b, co0, d, h=0); plane-to-plane stride = D*H = 4096 rows
    const size_t base0 = ((size_t)(b * COUT + c * 27 + i * 9) * D_ + d) * H_;
    float4* const pw0  = out4 + (base0 + h0) * ROWQ + lane;   // jl=0 plane, row h0

    if ((unsigned)din >= (unsigned)D_) {
        // whole 9-plane group is padding -> zero-stream all of it
        const float4 z = make_float4(0.f, 0.f, 0.f, 0.f);
        #pragma unroll
        for (int jl = 0; jl < 9; ++jl) {
            float4* p = pw0 + (size_t)jl * D_ * H_ * ROWQ;
            #pragma unroll
            for (int k = 0; k < 16; ++k)
                __stcs(p + (size_t)k * ROWQ, z);
        }
        return;
    }

    // ---- load slab + halo: input rows hin = h0-1 .. h0+16 ----
    const float4* const xp =
        reinterpret_cast<const float4*>(x) +
        (((size_t)(b * C_ + c) * D_ + din) * H_) * ROWQ + lane;
    float4 v[18];
    #pragma unroll
    for (int k = 0; k < 18; ++k) {
        const int hin = h0 - 1 + k;
        v[k] = ((unsigned)hin < (unsigned)H_)
             ? __ldg(xp + (size_t)hin * ROWQ)
             : make_float4(0.f, 0.f, 0.f, 0.f);
    }

    // ---- store 9 planes, each 16 sequential rows ----
    const size_t PS = (size_t)D_ * H_ * ROWQ;   // plane stride in float4
    store_plane<0, 0>(v, pw0 + 0 * PS, lane);
    store_plane<0, 1>(v, pw0 + 1 * PS, lane);
    store_plane<0, 2>(v, pw0 + 2 * PS, lane);
    store_plane<1, 0>(v, pw0 + 3 * PS, lane);
    store_plane<1, 1>(v, pw0 + 4 * PS, lane);
    store_plane<1, 2>(v, pw0 + 5 * PS, lane);
    store_plane<2, 0>(v, pw0 + 6 * PS, lane);
    store_plane<2, 1>(v, pw0 + 7 * PS, lane);
    store_plane<2, 2>(v, pw0 + 8 * PS, lane);
}

extern "C" void kernel_launch(void* const* d_in, const int* in_sizes, int n_in,
                              void* d_out, int out_size) {
    const float* x = (const float*)d_in[0];
    float* out = (float*)d_out;
    (void)in_sizes; (void)n_in; (void)out_size;

    dim3 grid(D_, 9, B_);               // (32, 9, 2) = 576 blocks, 256 thr
    patch3d_hybrid<<<grid, 256>>>(x, out);
}

// round 10
// speedup vs baseline: 1.0675x; 1.0675x over previous
#include <cuda_runtime.h>

// PatchExtractor3d: out[b, c*27 + i*9 + j*3 + l, d, h, w] = xpad[b, c, d+i, h+j, w+l]
// x [2,3,32,128,128] fp32 -> out [2,81,32,128,128] fp32, pad=1, K=3.
//
// HYBRID v2 (properly sized): block = (b, c, i, d, hchunk). One input-plane
// slab feeds the same 32 h-rows of 9 contiguous output planes (j,l).
// Warp owns 4 rows: 6 front-batched LDG.128 (slab+halo), 36 streaming STG.128.
// Read amplification 27x -> 1.5x vs gather; grid=2304, occ ~50%.

static constexpr int B_  = 2;
static constexpr int C_  = 3;
static constexpr int D_  = 32;
static constexpr int H_  = 128;
static constexpr int W_  = 128;
static constexpr int COUT = C_ * 27;   // 81
static constexpr int ROWQ = W_ / 4;    // 32 float4 per row

template<int L>
__device__ __forceinline__ float4 shift_row(float4 cur, int lane) {
    if (L == 1) return cur;
    float4 r;
    if (L == 0) {                       // out[w] = in[w-1]
        const float pw = __shfl_up_sync(0xffffffffu, cur.w, 1);
        r.x = (lane == 0) ? 0.f : pw;
        r.y = cur.x; r.z = cur.y; r.w = cur.z;
    } else {                            // out[w] = in[w+1]
        const float nx = __shfl_down_sync(0xffffffffu, cur.x, 1);
        r.x = cur.y; r.y = cur.z; r.z = cur.w;
        r.w = (lane == 31) ? 0.f : nx;
    }
    return r;
}

// Store 4 sequential rows of one (J,L) plane from registers v[J..J+3].
template<int J, int L>
__device__ __forceinline__ void store_plane4(const float4* v,
                                             float4* __restrict__ p,
                                             int lane) {
    #pragma unroll
    for (int k = 0; k < 4; ++k)
        __stcs(p + (size_t)k * ROWQ, shift_row<L>(v[k + J], lane));
}

__global__ __launch_bounds__(256, 4)
void patch3d_hybrid2(const float* __restrict__ x, float* __restrict__ out) {
    const int d   = blockIdx.x;          // 0..31
    const int ci  = blockIdx.y;          // 0..8 : c*3 + i
    const int bz  = blockIdx.z;          // 0..7 : b*4 + hchunk
    const int c   = ci / 3;
    const int i   = ci - c * 3;
    const int b   = bz >> 2;
    const int hc  = bz & 3;
    const int din = d + i - 1;

    const int warp = threadIdx.x >> 5;
    const int lane = threadIdx.x & 31;
    const int h0   = hc * 32 + warp * 4;          // this warp's first row

    float4* const out4 = reinterpret_cast<float4*>(out);
    const size_t base0 = ((size_t)(b * COUT + c * 27 + i * 9) * D_ + d) * H_;
    float4* const pw0  = out4 + (base0 + h0) * ROWQ + lane;  // jl=0 plane
    const size_t PS = (size_t)D_ * H_ * ROWQ;                 // plane stride

    if ((unsigned)din >= (unsigned)D_) {
        // whole 9-plane group is padding -> zero-stream this warp's rows
        const float4 z = make_float4(0.f, 0.f, 0.f, 0.f);
        #pragma unroll
        for (int jl = 0; jl < 9; ++jl) {
            float4* p = pw0 + (size_t)jl * PS;
            #pragma unroll
            for (int k = 0; k < 4; ++k)
                __stcs(p + (size_t)k * ROWQ, z);
        }
        return;
    }

    // ---- load 4-row slab + halo: input rows hin = h0-1 .. h0+4 ----
    const float4* const xp =
        reinterpret_cast<const float4*>(x) +
        (((size_t)(b * C_ + c) * D_ + din) * H_) * ROWQ + lane;
    float4 v[6];
    #pragma unroll
    for (int k = 0; k < 6; ++k) {
        const int hin = h0 - 1 + k;
        v[k] = ((unsigned)hin < (unsigned)H_)
             ? __ldg(xp + (size_t)hin * ROWQ)
             : make_float4(0.f, 0.f, 0.f, 0.f);
    }

    // ---- store 9 planes x 4 sequential rows each ----
    store_plane4<0, 0>(v, pw0 + 0 * PS, lane);
    store_plane4<0, 1>(v, pw0 + 1 * PS, lane);
    store_plane4<0, 2>(v, pw0 + 2 * PS, lane);
    store_plane4<1, 0>(v, pw0 + 3 * PS, lane);
    store_plane4<1, 1>(v, pw0 + 4 * PS, lane);
    store_plane4<1, 2>(v, pw0 + 5 * PS, lane);
    store_plane4<2, 0>(v, pw0 + 6 * PS, lane);
    store_plane4<2, 1>(v, pw0 + 7 * PS, lane);
    store_plane4<2, 2>(v, pw0 + 8 * PS, lane);
}

extern "C" void kernel_launch(void* const* d_in, const int* in_sizes, int n_in,
                              void* d_out, int out_size) {
    const float* x = (const float*)d_in[0];
    float* out = (float*)d_out;
    (void)in_sizes; (void)n_in; (void)out_size;

    dim3 grid(D_, 9, 8);                // (32, 9, 8) = 2304 blocks, 256 thr
    patch3d_hybrid2<<<grid, 256>>>(x, out);
}